// round 2
// baseline (speedup 1.0000x reference)
#include <cuda_runtime.h>
#include <math.h>

#define L_TOK  4680
#define DIM_   1536
#define NH     12
#define HD     128
#define FRAME  1560
#define WW     52
#define SINK   1
#define LOCAL  2

// Scratch (no cudaMalloc allowed)
__device__ float g_q[L_TOK * DIM_];
__device__ float g_k[L_TOK * DIM_];
__device__ float g_v[L_TOK * DIM_];
__device__ float g_a[L_TOK * DIM_];

// ---------------------------------------------------------------------------
// C[M,N] = A[M,K] @ B[N,K]^T + bias   (A row-major, B row-major "NT" gemm)
// BM=128, BN=128, BK=16, 256 threads, 8x8 microtile
// ---------------------------------------------------------------------------
__global__ void gemm_bias_kernel(const float* __restrict__ A,
                                 const float* __restrict__ B,
                                 const float* __restrict__ bias,
                                 float* __restrict__ C,
                                 int M, int N, int K) {
    __shared__ float As[16][132];
    __shared__ float Bs[16][132];
    const int tid = threadIdx.x;
    const int tx = tid & 15, ty = tid >> 4;
    const int m0 = blockIdx.y * 128, n0 = blockIdx.x * 128;

    float acc[8][8];
#pragma unroll
    for (int i = 0; i < 8; i++)
#pragma unroll
        for (int j = 0; j < 8; j++) acc[i][j] = 0.f;

    for (int k0 = 0; k0 < K; k0 += 16) {
#pragma unroll
        for (int it = 0; it < 2; it++) {
            int i = tid + it * 256;          // 0..511 -> 128 rows x 4 float4 segs
            int row = i >> 2, seg = (i & 3) * 4;
            float4 va = make_float4(0.f, 0.f, 0.f, 0.f);
            if (m0 + row < M)
                va = *(const float4*)(A + (size_t)(m0 + row) * K + k0 + seg);
            As[seg + 0][row] = va.x; As[seg + 1][row] = va.y;
            As[seg + 2][row] = va.z; As[seg + 3][row] = va.w;
        }
#pragma unroll
        for (int it = 0; it < 2; it++) {
            int i = tid + it * 256;
            int row = i >> 2, seg = (i & 3) * 4;
            float4 vb = *(const float4*)(B + (size_t)(n0 + row) * K + k0 + seg);
            Bs[seg + 0][row] = vb.x; Bs[seg + 1][row] = vb.y;
            Bs[seg + 2][row] = vb.z; Bs[seg + 3][row] = vb.w;
        }
        __syncthreads();
#pragma unroll
        for (int kk = 0; kk < 16; kk++) {
            float a[8], b[8];
#pragma unroll
            for (int i = 0; i < 8; i++) a[i] = As[kk][ty * 8 + i];
#pragma unroll
            for (int j = 0; j < 8; j++) b[j] = Bs[kk][tx * 8 + j];
#pragma unroll
            for (int i = 0; i < 8; i++)
#pragma unroll
                for (int j = 0; j < 8; j++)
                    acc[i][j] = fmaf(a[i], b[j], acc[i][j]);
        }
        __syncthreads();
    }
#pragma unroll
    for (int i = 0; i < 8; i++) {
        int m = m0 + ty * 8 + i;
        if (m >= M) continue;
#pragma unroll
        for (int j = 0; j < 8; j++) {
            int n = n0 + tx * 8 + j;
            C[(size_t)m * N + n] = acc[i][j] + bias[n];
        }
    }
}

// ---------------------------------------------------------------------------
// In-place RMSNorm over DIM, then 3D RoPE (pairs: 0..21 -> f, 22..42 -> h,
// 43..63 -> w, per 128-d head).  One block per token.
// ---------------------------------------------------------------------------
__global__ void norm_rope_kernel(float* __restrict__ data,
                                 const float* __restrict__ g,
                                 const float* __restrict__ freqs) {
    const int t = blockIdx.x;
    const int tid = threadIdx.x;
    float* row = data + (size_t)t * DIM_;

    float ss = 0.f;
    for (int c = tid; c < DIM_; c += 256) { float v = row[c]; ss += v * v; }
#pragma unroll
    for (int o = 16; o; o >>= 1) ss += __shfl_xor_sync(0xffffffffu, ss, o);

    __shared__ float red[8];
    __shared__ float inv_s;
    if ((tid & 31) == 0) red[tid >> 5] = ss;
    __syncthreads();
    if (tid == 0) {
        float tot = 0.f;
#pragma unroll
        for (int i = 0; i < 8; i++) tot += red[i];
        inv_s = rsqrtf(tot / (float)DIM_ + 1e-6f);
    }
    __syncthreads();
    const float inv = inv_s;

    const int f = t / FRAME, rem = t % FRAME;
    const int hh = rem / WW, ww = rem % WW;

    for (int p = tid; p < DIM_ / 2; p += 256) {
        int pin = p & 63;
        int pos = (pin < 22) ? f : ((pin < 43) ? hh : ww);
        float cs = freqs[(pos * 64 + pin) * 2 + 0];
        float sn = freqs[(pos * 64 + pin) * 2 + 1];
        int c = p * 2;
        float a = row[c]     * inv * g[c];
        float b = row[c + 1] * inv * g[c + 1];
        row[c]     = a * cs - b * sn;
        row[c + 1] = a * sn + b * cs;
    }
}

// ---------------------------------------------------------------------------
// fp32 flash attention, BM=BN=64, online softmax.
// grid: (ceil(L/64), NH), 256 threads (16x16), dynamic smem.
// ---------------------------------------------------------------------------
__global__ void attn_kernel(const float* __restrict__ Q,
                            const float* __restrict__ K,
                            const float* __restrict__ V,
                            float* __restrict__ O) {
    extern __shared__ float sm[];
    float* Qs  = sm;                 // [128][68]  (d-major, transposed)
    float* KVs = Qs + 128 * 68;      // K: [128][68] transposed / V: [64][132]
    float* Ss  = KVs + 128 * 68;     // [64][68]
    float* mS  = Ss + 64 * 68;       // [64]
    float* lS  = mS + 64;            // [64]
    float* aS  = lS + 64;            // [64]

    const int tid = threadIdx.x;
    const int tx = tid & 15, ty = tid >> 4;
    const int h = blockIdx.y;
    const int q0 = blockIdx.x * 64;
    const float scale = 0.08838834764831845f;  // 1/sqrt(128)

    // Q tile, transposed: Qs[d][row]
    for (int i = tid; i < 64 * 32; i += 256) {
        int row = i >> 5, seg = (i & 31) * 4;
        float4 v = make_float4(0.f, 0.f, 0.f, 0.f);
        if (q0 + row < L_TOK)
            v = *(const float4*)(Q + (size_t)(q0 + row) * DIM_ + h * HD + seg);
        Qs[(seg + 0) * 68 + row] = v.x;
        Qs[(seg + 1) * 68 + row] = v.y;
        Qs[(seg + 2) * 68 + row] = v.z;
        Qs[(seg + 3) * 68 + row] = v.w;
    }
    if (tid < 64) { mS[tid] = -INFINITY; lS[tid] = 0.f; aS[tid] = 0.f; }

    float o_acc[4][8];
#pragma unroll
    for (int i = 0; i < 4; i++)
#pragma unroll
        for (int j = 0; j < 8; j++) o_acc[i][j] = 0.f;

    int qf_r[4];
#pragma unroll
    for (int i = 0; i < 4; i++) {
        int r = q0 + ty * 4 + i;
        qf_r[i] = (r < L_TOK ? r : L_TOK - 1) / FRAME;
    }

    const int qmax = min(q0 + 63, L_TOK - 1);
    const int kend = min(L_TOK, (qmax / FRAME + 1) * FRAME);
    const int ntiles = (kend + 63) >> 6;

    for (int t = 0; t < ntiles; t++) {
        const int k0 = t * 64;
        __syncthreads();  // protect Qs/KVs/Ss from previous phase
        // K tile, transposed
        for (int i = tid; i < 64 * 32; i += 256) {
            int row = i >> 5, seg = (i & 31) * 4;
            float4 v = make_float4(0.f, 0.f, 0.f, 0.f);
            if (k0 + row < L_TOK)
                v = *(const float4*)(K + (size_t)(k0 + row) * DIM_ + h * HD + seg);
            KVs[(seg + 0) * 68 + row] = v.x;
            KVs[(seg + 1) * 68 + row] = v.y;
            KVs[(seg + 2) * 68 + row] = v.z;
            KVs[(seg + 3) * 68 + row] = v.w;
        }
        __syncthreads();

        // S = Q K^T (4x4 microtile per thread)
        float s[4][4];
#pragma unroll
        for (int i = 0; i < 4; i++)
#pragma unroll
            for (int j = 0; j < 4; j++) s[i][j] = 0.f;
#pragma unroll 4
        for (int kk = 0; kk < 128; kk++) {
            float a[4], b[4];
#pragma unroll
            for (int i = 0; i < 4; i++) a[i] = Qs[kk * 68 + ty * 4 + i];
#pragma unroll
            for (int j = 0; j < 4; j++) b[j] = KVs[kk * 68 + tx * 4 + j];
#pragma unroll
            for (int i = 0; i < 4; i++)
#pragma unroll
                for (int j = 0; j < 4; j++)
                    s[i][j] = fmaf(a[i], b[j], s[i][j]);
        }

        // mask + scale + write to Ss
#pragma unroll
        for (int j = 0; j < 4; j++) {
            int kidx = k0 + tx * 4 + j;
            int kf = kidx / FRAME;
            bool kvalid = kidx < L_TOK;
#pragma unroll
            for (int i = 0; i < 4; i++) {
                bool allow = kvalid && (kf <= qf_r[i]) &&
                             ((kf < SINK) || (qf_r[i] - kf < LOCAL));
                Ss[(ty * 4 + i) * 68 + tx * 4 + j] = allow ? s[i][j] * scale : -INFINITY;
            }
        }
        __syncthreads();

        // online softmax: 4 threads per row
        {
            int r = tid >> 2, q4 = tid & 3;
            float mloc = -INFINITY;
#pragma unroll
            for (int c = 0; c < 16; c++)
                mloc = fmaxf(mloc, Ss[r * 68 + q4 * 16 + c]);
            mloc = fmaxf(mloc, __shfl_xor_sync(0xffffffffu, mloc, 1));
            mloc = fmaxf(mloc, __shfl_xor_sync(0xffffffffu, mloc, 2));
            float mold = mS[r];
            float mnew = fmaxf(mold, mloc);
            float sum = 0.f;
#pragma unroll
            for (int c = 0; c < 16; c++) {
                float p = __expf(Ss[r * 68 + q4 * 16 + c] - mnew);
                Ss[r * 68 + q4 * 16 + c] = p;
                sum += p;
            }
            sum += __shfl_xor_sync(0xffffffffu, sum, 1);
            sum += __shfl_xor_sync(0xffffffffu, sum, 2);
            if (q4 == 0) {
                float alpha = __expf(mold - mnew);  // -inf -> 0 on first tile
                mS[r] = mnew;
                aS[r] = alpha;
                lS[r] = lS[r] * alpha + sum;
            }
        }
        __syncthreads();

        // V tile, row-major [key][col] (reuses KVs; K fully consumed)
        for (int i = tid; i < 64 * 32; i += 256) {
            int row = i >> 5, seg = (i & 31) * 4;
            float4 v = make_float4(0.f, 0.f, 0.f, 0.f);
            if (k0 + row < L_TOK)
                v = *(const float4*)(V + (size_t)(k0 + row) * DIM_ + h * HD + seg);
            *(float4*)(KVs + row * 132 + seg) = v;
        }
        __syncthreads();

        // rescale + O += P V
        float alpha_r[4];
#pragma unroll
        for (int i = 0; i < 4; i++) alpha_r[i] = aS[ty * 4 + i];
#pragma unroll
        for (int i = 0; i < 4; i++)
#pragma unroll
            for (int j = 0; j < 8; j++) o_acc[i][j] *= alpha_r[i];

#pragma unroll 4
        for (int key = 0; key < 64; key++) {
            float p[4];
#pragma unroll
            for (int i = 0; i < 4; i++) p[i] = Ss[(ty * 4 + i) * 68 + key];
            float4 v0 = *(float4*)(KVs + key * 132 + tx * 8);
            float4 v1 = *(float4*)(KVs + key * 132 + tx * 8 + 4);
            float vv[8] = {v0.x, v0.y, v0.z, v0.w, v1.x, v1.y, v1.z, v1.w};
#pragma unroll
            for (int i = 0; i < 4; i++)
#pragma unroll
                for (int j = 0; j < 8; j++)
                    o_acc[i][j] = fmaf(p[i], vv[j], o_acc[i][j]);
        }
    }

    // epilogue
#pragma unroll
    for (int i = 0; i < 4; i++) {
        int r = q0 + ty * 4 + i;
        if (r >= L_TOK) continue;
        float linv = 1.f / lS[ty * 4 + i];
#pragma unroll
        for (int j = 0; j < 8; j++)
            O[(size_t)r * DIM_ + h * HD + tx * 8 + j] = o_acc[i][j] * linv;
    }
}

// ---------------------------------------------------------------------------
extern "C" void kernel_launch(void* const* d_in, const int* in_sizes, int n_in,
                              void* d_out, int out_size) {
    const float* x  = (const float*)d_in[0];
    const float* wq = (const float*)d_in[1];
    const float* bq = (const float*)d_in[2];
    const float* wk = (const float*)d_in[3];
    const float* bk = (const float*)d_in[4];
    const float* wv = (const float*)d_in[5];
    const float* bv = (const float*)d_in[6];
    const float* wo = (const float*)d_in[7];
    const float* bo = (const float*)d_in[8];
    const float* gq = (const float*)d_in[9];
    const float* gk = (const float*)d_in[10];
    const float* fr = (const float*)d_in[11];
    float* out = (float*)d_out;

    float *q, *k, *v, *a;
    cudaGetSymbolAddress((void**)&q, g_q);
    cudaGetSymbolAddress((void**)&k, g_k);
    cudaGetSymbolAddress((void**)&v, g_v);
    cudaGetSymbolAddress((void**)&a, g_a);

    dim3 gg(DIM_ / 128, (L_TOK + 127) / 128);
    gemm_bias_kernel<<<gg, 256>>>(x, wq, bq, q, L_TOK, DIM_, DIM_);
    gemm_bias_kernel<<<gg, 256>>>(x, wk, bk, k, L_TOK, DIM_, DIM_);
    gemm_bias_kernel<<<gg, 256>>>(x, wv, bv, v, L_TOK, DIM_, DIM_);

    norm_rope_kernel<<<L_TOK, 256>>>(q, gq, fr);
    norm_rope_kernel<<<L_TOK, 256>>>(k, gk, fr);

    size_t smem = (size_t)(128 * 68 + 128 * 68 + 64 * 68 + 192) * sizeof(float);
    cudaFuncSetAttribute(attn_kernel, cudaFuncAttributeMaxDynamicSharedMemorySize,
                         (int)smem);
    attn_kernel<<<dim3((L_TOK + 63) / 64, NH), 256, smem>>>(q, k, v, a);

    gemm_bias_kernel<<<gg, 256>>>(a, wo, bo, out, L_TOK, DIM_, DIM_);
}

// round 3
// speedup vs baseline: 1.1794x; 1.1794x over previous
#include <cuda_runtime.h>
#include <cuda_bf16.h>
#include <math.h>

#define L_TOK  4680
#define DIM_   1536
#define NH     12
#define HD     128
#define FRAME  1560
#define WW     52
#define SINK   1
#define LOCAL  2

// Scratch (no cudaMalloc allowed)
__device__ float g_q[L_TOK * DIM_];
__device__ float g_k[L_TOK * DIM_];
__device__ float g_v[L_TOK * DIM_];
__device__ float g_a[L_TOK * DIM_];
__device__ __nv_bfloat16 g_act_hi[L_TOK * DIM_];
__device__ __nv_bfloat16 g_act_lo[L_TOK * DIM_];
__device__ __nv_bfloat16 g_w_hi[DIM_ * DIM_];
__device__ __nv_bfloat16 g_w_lo[DIM_ * DIM_];

// ---------------------------------------------------------------------------
// Split fp32 -> (hi, lo) bf16 planes.  x ~= hi + lo, |x - hi - lo| ~ 2^-18 |x|
// ---------------------------------------------------------------------------
__global__ void split_kernel(const float4* __restrict__ src,
                             __nv_bfloat162* __restrict__ hi,
                             __nv_bfloat162* __restrict__ lo,
                             int n4) {
    int i = blockIdx.x * blockDim.x + threadIdx.x;
    if (i >= n4) return;
    float4 f = src[i];
    __nv_bfloat16 h0 = __float2bfloat16_rn(f.x);
    __nv_bfloat16 h1 = __float2bfloat16_rn(f.y);
    __nv_bfloat16 h2 = __float2bfloat16_rn(f.z);
    __nv_bfloat16 h3 = __float2bfloat16_rn(f.w);
    __nv_bfloat16 l0 = __float2bfloat16_rn(f.x - __bfloat162float(h0));
    __nv_bfloat16 l1 = __float2bfloat16_rn(f.y - __bfloat162float(h1));
    __nv_bfloat16 l2 = __float2bfloat16_rn(f.z - __bfloat162float(h2));
    __nv_bfloat16 l3 = __float2bfloat16_rn(f.w - __bfloat162float(h3));
    hi[i * 2 + 0] = __halves2bfloat162(h0, h1);
    hi[i * 2 + 1] = __halves2bfloat162(h2, h3);
    lo[i * 2 + 0] = __halves2bfloat162(l0, l1);
    lo[i * 2 + 1] = __halves2bfloat162(l2, l3);
}

// ---------------------------------------------------------------------------
// C[M,N] = A[M,K] @ B[N,K]^T + bias, split-bf16 compensated tensor-core GEMM.
// A,B given as hi/lo bf16 planes.  K = N = 1536 fixed.  BM=BN=128, BK=32,
// 256 threads = 8 warps (2 x 4), each warp 64x32, m16n8k16 fragments.
// ---------------------------------------------------------------------------
#define GK 1536
#define SPITCH 40   // smem row pitch in bf16 (80 bytes: 16B aligned, bank-clean)

__device__ __forceinline__ void mma_bf16(float* c, const unsigned* a,
                                         unsigned b0, unsigned b1) {
    asm volatile(
        "mma.sync.aligned.m16n8k16.row.col.f32.bf16.bf16.f32 "
        "{%0,%1,%2,%3}, {%4,%5,%6,%7}, {%8,%9}, {%0,%1,%2,%3};"
        : "+f"(c[0]), "+f"(c[1]), "+f"(c[2]), "+f"(c[3])
        : "r"(a[0]), "r"(a[1]), "r"(a[2]), "r"(a[3]), "r"(b0), "r"(b1));
}

__global__ __launch_bounds__(256, 2)
void gemm_bf16s_kernel(const __nv_bfloat16* __restrict__ Ah,
                       const __nv_bfloat16* __restrict__ Al,
                       const __nv_bfloat16* __restrict__ Bh,
                       const __nv_bfloat16* __restrict__ Bl,
                       const float* __restrict__ bias,
                       float* __restrict__ C, int M) {
    __shared__ __nv_bfloat16 Ash[128 * SPITCH];
    __shared__ __nv_bfloat16 Asl[128 * SPITCH];
    __shared__ __nv_bfloat16 Bsh[128 * SPITCH];
    __shared__ __nv_bfloat16 Bsl[128 * SPITCH];

    const int tid = threadIdx.x;
    const int lane = tid & 31, wid = tid >> 5;
    const int wm = (wid & 1) * 64;     // warp row offset in block
    const int wn = (wid >> 1) * 32;    // warp col offset in block
    const int m0 = blockIdx.y * 128, n0 = blockIdx.x * 128;

    float acc[4][4][4];
#pragma unroll
    for (int i = 0; i < 4; i++)
#pragma unroll
        for (int j = 0; j < 4; j++)
#pragma unroll
            for (int r = 0; r < 4; r++) acc[i][j][r] = 0.f;

    const int ldrow = tid >> 1;          // 0..127
    const int ldhalf = (tid & 1) * 16;   // bf16 col offset 0 / 16
    const bool mok = (m0 + ldrow) < M;
    const size_t a_off = (size_t)(m0 + ldrow) * GK + ldhalf;
    const size_t b_off = (size_t)(n0 + ldrow) * GK + ldhalf;

    const int quad = lane >> 2, tq = (lane & 3) * 2;

    for (int k0 = 0; k0 < GK; k0 += 32) {
        // ---- global -> smem (16 bf16 = 2 x uint4 per plane per thread) ----
        uint4 z = make_uint4(0u, 0u, 0u, 0u);
        uint4 vah0 = z, vah1 = z, val0 = z, val1 = z;
        if (mok) {
            const uint4* p = (const uint4*)(Ah + a_off + k0);
            vah0 = p[0]; vah1 = p[1];
            p = (const uint4*)(Al + a_off + k0);
            val0 = p[0]; val1 = p[1];
        }
        const uint4* pb = (const uint4*)(Bh + b_off + k0);
        uint4 vbh0 = pb[0], vbh1 = pb[1];
        pb = (const uint4*)(Bl + b_off + k0);
        uint4 vbl0 = pb[0], vbl1 = pb[1];

        uint4* s = (uint4*)(Ash + ldrow * SPITCH + ldhalf);
        s[0] = vah0; s[1] = vah1;
        s = (uint4*)(Asl + ldrow * SPITCH + ldhalf);
        s[0] = val0; s[1] = val1;
        s = (uint4*)(Bsh + ldrow * SPITCH + ldhalf);
        s[0] = vbh0; s[1] = vbh1;
        s = (uint4*)(Bsl + ldrow * SPITCH + ldhalf);
        s[0] = vbl0; s[1] = vbl1;
        __syncthreads();

#pragma unroll
        for (int ks = 0; ks < 2; ks++) {
            const int kb = ks * 16;
            unsigned ah[4][4], al[4][4];
#pragma unroll
            for (int mt = 0; mt < 4; mt++) {
                int r = wm + mt * 16 + quad;
                ah[mt][0] = *(const unsigned*)(Ash + r * SPITCH + kb + tq);
                ah[mt][1] = *(const unsigned*)(Ash + (r + 8) * SPITCH + kb + tq);
                ah[mt][2] = *(const unsigned*)(Ash + r * SPITCH + kb + tq + 8);
                ah[mt][3] = *(const unsigned*)(Ash + (r + 8) * SPITCH + kb + tq + 8);
                al[mt][0] = *(const unsigned*)(Asl + r * SPITCH + kb + tq);
                al[mt][1] = *(const unsigned*)(Asl + (r + 8) * SPITCH + kb + tq);
                al[mt][2] = *(const unsigned*)(Asl + r * SPITCH + kb + tq + 8);
                al[mt][3] = *(const unsigned*)(Asl + (r + 8) * SPITCH + kb + tq + 8);
            }
#pragma unroll
            for (int nt = 0; nt < 4; nt++) {
                int bn = wn + nt * 8 + quad;
                unsigned bh0 = *(const unsigned*)(Bsh + bn * SPITCH + kb + tq);
                unsigned bh1 = *(const unsigned*)(Bsh + bn * SPITCH + kb + tq + 8);
                unsigned bl0 = *(const unsigned*)(Bsl + bn * SPITCH + kb + tq);
                unsigned bl1 = *(const unsigned*)(Bsl + bn * SPITCH + kb + tq + 8);
#pragma unroll
                for (int mt = 0; mt < 4; mt++) {
                    mma_bf16(acc[mt][nt], ah[mt], bh0, bh1);  // hi*hi
                    mma_bf16(acc[mt][nt], al[mt], bh0, bh1);  // lo*hi
                    mma_bf16(acc[mt][nt], ah[mt], bl0, bl1);  // hi*lo
                }
            }
        }
        __syncthreads();
    }

    // ---- epilogue ----
#pragma unroll
    for (int mt = 0; mt < 4; mt++) {
        int r0 = m0 + wm + mt * 16 + quad;
#pragma unroll
        for (int nt = 0; nt < 4; nt++) {
            int col = n0 + wn + nt * 8 + tq;
            float b0 = bias[col], b1 = bias[col + 1];
            if (r0 < M) {
                float2 v = make_float2(acc[mt][nt][0] + b0, acc[mt][nt][1] + b1);
                *(float2*)(C + (size_t)r0 * GK + col) = v;
            }
            if (r0 + 8 < M) {
                float2 v = make_float2(acc[mt][nt][2] + b0, acc[mt][nt][3] + b1);
                *(float2*)(C + (size_t)(r0 + 8) * GK + col) = v;
            }
        }
    }
}

// ---------------------------------------------------------------------------
// In-place RMSNorm over DIM, then 3D RoPE.  One block per token.
// ---------------------------------------------------------------------------
__global__ void norm_rope_kernel(float* __restrict__ data,
                                 const float* __restrict__ g,
                                 const float* __restrict__ freqs) {
    const int t = blockIdx.x;
    const int tid = threadIdx.x;
    float* row = data + (size_t)t * DIM_;

    float ss = 0.f;
    for (int c = tid; c < DIM_; c += 256) { float v = row[c]; ss += v * v; }
#pragma unroll
    for (int o = 16; o; o >>= 1) ss += __shfl_xor_sync(0xffffffffu, ss, o);

    __shared__ float red[8];
    __shared__ float inv_s;
    if ((tid & 31) == 0) red[tid >> 5] = ss;
    __syncthreads();
    if (tid == 0) {
        float tot = 0.f;
#pragma unroll
        for (int i = 0; i < 8; i++) tot += red[i];
        inv_s = rsqrtf(tot / (float)DIM_ + 1e-6f);
    }
    __syncthreads();
    const float inv = inv_s;

    const int f = t / FRAME, rem = t % FRAME;
    const int hh = rem / WW, ww = rem % WW;

    for (int p = tid; p < DIM_ / 2; p += 256) {
        int pin = p & 63;
        int pos = (pin < 22) ? f : ((pin < 43) ? hh : ww);
        float cs = freqs[(pos * 64 + pin) * 2 + 0];
        float sn = freqs[(pos * 64 + pin) * 2 + 1];
        int c = p * 2;
        float a = row[c]     * inv * g[c];
        float b = row[c + 1] * inv * g[c + 1];
        row[c]     = a * cs - b * sn;
        row[c + 1] = a * sn + b * cs;
    }
}

// ---------------------------------------------------------------------------
// fp32 flash attention, BM=BN=64, online softmax. (unchanged, verified)
// ---------------------------------------------------------------------------
__global__ void attn_kernel(const float* __restrict__ Q,
                            const float* __restrict__ K,
                            const float* __restrict__ V,
                            float* __restrict__ O) {
    extern __shared__ float sm[];
    float* Qs  = sm;                 // [128][68]  (d-major, transposed)
    float* KVs = Qs + 128 * 68;      // K: [128][68] transposed / V: [64][132]
    float* Ss  = KVs + 128 * 68;     // [64][68]
    float* mS  = Ss + 64 * 68;       // [64]
    float* lS  = mS + 64;            // [64]
    float* aS  = lS + 64;            // [64]

    const int tid = threadIdx.x;
    const int tx = tid & 15, ty = tid >> 4;
    const int h = blockIdx.y;
    const int q0 = blockIdx.x * 64;
    const float scale = 0.08838834764831845f;  // 1/sqrt(128)

    for (int i = tid; i < 64 * 32; i += 256) {
        int row = i >> 5, seg = (i & 31) * 4;
        float4 v = make_float4(0.f, 0.f, 0.f, 0.f);
        if (q0 + row < L_TOK)
            v = *(const float4*)(Q + (size_t)(q0 + row) * DIM_ + h * HD + seg);
        Qs[(seg + 0) * 68 + row] = v.x;
        Qs[(seg + 1) * 68 + row] = v.y;
        Qs[(seg + 2) * 68 + row] = v.z;
        Qs[(seg + 3) * 68 + row] = v.w;
    }
    if (tid < 64) { mS[tid] = -INFINITY; lS[tid] = 0.f; aS[tid] = 0.f; }

    float o_acc[4][8];
#pragma unroll
    for (int i = 0; i < 4; i++)
#pragma unroll
        for (int j = 0; j < 8; j++) o_acc[i][j] = 0.f;

    int qf_r[4];
#pragma unroll
    for (int i = 0; i < 4; i++) {
        int r = q0 + ty * 4 + i;
        qf_r[i] = (r < L_TOK ? r : L_TOK - 1) / FRAME;
    }

    const int qmax = min(q0 + 63, L_TOK - 1);
    const int kend = min(L_TOK, (qmax / FRAME + 1) * FRAME);
    const int ntiles = (kend + 63) >> 6;

    for (int t = 0; t < ntiles; t++) {
        const int k0 = t * 64;
        __syncthreads();
        for (int i = tid; i < 64 * 32; i += 256) {
            int row = i >> 5, seg = (i & 31) * 4;
            float4 v = make_float4(0.f, 0.f, 0.f, 0.f);
            if (k0 + row < L_TOK)
                v = *(const float4*)(K + (size_t)(k0 + row) * DIM_ + h * HD + seg);
            KVs[(seg + 0) * 68 + row] = v.x;
            KVs[(seg + 1) * 68 + row] = v.y;
            KVs[(seg + 2) * 68 + row] = v.z;
            KVs[(seg + 3) * 68 + row] = v.w;
        }
        __syncthreads();

        float s[4][4];
#pragma unroll
        for (int i = 0; i < 4; i++)
#pragma unroll
            for (int j = 0; j < 4; j++) s[i][j] = 0.f;
#pragma unroll 4
        for (int kk = 0; kk < 128; kk++) {
            float a[4], b[4];
#pragma unroll
            for (int i = 0; i < 4; i++) a[i] = Qs[kk * 68 + ty * 4 + i];
#pragma unroll
            for (int j = 0; j < 4; j++) b[j] = KVs[kk * 68 + tx * 4 + j];
#pragma unroll
            for (int i = 0; i < 4; i++)
#pragma unroll
                for (int j = 0; j < 4; j++)
                    s[i][j] = fmaf(a[i], b[j], s[i][j]);
        }

#pragma unroll
        for (int j = 0; j < 4; j++) {
            int kidx = k0 + tx * 4 + j;
            int kf = kidx / FRAME;
            bool kvalid = kidx < L_TOK;
#pragma unroll
            for (int i = 0; i < 4; i++) {
                bool allow = kvalid && (kf <= qf_r[i]) &&
                             ((kf < SINK) || (qf_r[i] - kf < LOCAL));
                Ss[(ty * 4 + i) * 68 + tx * 4 + j] = allow ? s[i][j] * scale : -INFINITY;
            }
        }
        __syncthreads();

        {
            int r = tid >> 2, q4 = tid & 3;
            float mloc = -INFINITY;
#pragma unroll
            for (int c = 0; c < 16; c++)
                mloc = fmaxf(mloc, Ss[r * 68 + q4 * 16 + c]);
            mloc = fmaxf(mloc, __shfl_xor_sync(0xffffffffu, mloc, 1));
            mloc = fmaxf(mloc, __shfl_xor_sync(0xffffffffu, mloc, 2));
            float mold = mS[r];
            float mnew = fmaxf(mold, mloc);
            float sum = 0.f;
#pragma unroll
            for (int c = 0; c < 16; c++) {
                float p = __expf(Ss[r * 68 + q4 * 16 + c] - mnew);
                Ss[r * 68 + q4 * 16 + c] = p;
                sum += p;
            }
            sum += __shfl_xor_sync(0xffffffffu, sum, 1);
            sum += __shfl_xor_sync(0xffffffffu, sum, 2);
            if (q4 == 0) {
                float alpha = __expf(mold - mnew);
                mS[r] = mnew;
                aS[r] = alpha;
                lS[r] = lS[r] * alpha + sum;
            }
        }
        __syncthreads();

        for (int i = tid; i < 64 * 32; i += 256) {
            int row = i >> 5, seg = (i & 31) * 4;
            float4 v = make_float4(0.f, 0.f, 0.f, 0.f);
            if (k0 + row < L_TOK)
                v = *(const float4*)(V + (size_t)(k0 + row) * DIM_ + h * HD + seg);
            *(float4*)(KVs + row * 132 + seg) = v;
        }
        __syncthreads();

        float alpha_r[4];
#pragma unroll
        for (int i = 0; i < 4; i++) alpha_r[i] = aS[ty * 4 + i];
#pragma unroll
        for (int i = 0; i < 4; i++)
#pragma unroll
            for (int j = 0; j < 8; j++) o_acc[i][j] *= alpha_r[i];

#pragma unroll 4
        for (int key = 0; key < 64; key++) {
            float p[4];
#pragma unroll
            for (int i = 0; i < 4; i++) p[i] = Ss[(ty * 4 + i) * 68 + key];
            float4 v0 = *(float4*)(KVs + key * 132 + tx * 8);
            float4 v1 = *(float4*)(KVs + key * 132 + tx * 8 + 4);
            float vv[8] = {v0.x, v0.y, v0.z, v0.w, v1.x, v1.y, v1.z, v1.w};
#pragma unroll
            for (int i = 0; i < 4; i++)
#pragma unroll
                for (int j = 0; j < 8; j++)
                    o_acc[i][j] = fmaf(p[i], vv[j], o_acc[i][j]);
        }
    }

#pragma unroll
    for (int i = 0; i < 4; i++) {
        int r = q0 + ty * 4 + i;
        if (r >= L_TOK) continue;
        float linv = 1.f / lS[ty * 4 + i];
#pragma unroll
        for (int j = 0; j < 8; j++)
            O[(size_t)r * DIM_ + h * HD + tx * 8 + j] = o_acc[i][j] * linv;
    }
}

// ---------------------------------------------------------------------------
extern "C" void kernel_launch(void* const* d_in, const int* in_sizes, int n_in,
                              void* d_out, int out_size) {
    const float* x  = (const float*)d_in[0];
    const float* wq = (const float*)d_in[1];
    const float* bq = (const float*)d_in[2];
    const float* wk = (const float*)d_in[3];
    const float* bk = (const float*)d_in[4];
    const float* wv = (const float*)d_in[5];
    const float* bv = (const float*)d_in[6];
    const float* wo = (const float*)d_in[7];
    const float* bo = (const float*)d_in[8];
    const float* gq = (const float*)d_in[9];
    const float* gk = (const float*)d_in[10];
    const float* fr = (const float*)d_in[11];
    float* out = (float*)d_out;

    float *q, *k, *v, *a;
    __nv_bfloat16 *ah, *al, *wh, *wl;
    cudaGetSymbolAddress((void**)&q, g_q);
    cudaGetSymbolAddress((void**)&k, g_k);
    cudaGetSymbolAddress((void**)&v, g_v);
    cudaGetSymbolAddress((void**)&a, g_a);
    cudaGetSymbolAddress((void**)&ah, g_act_hi);
    cudaGetSymbolAddress((void**)&al, g_act_lo);
    cudaGetSymbolAddress((void**)&wh, g_w_hi);
    cudaGetSymbolAddress((void**)&wl, g_w_lo);

    const int nact4 = L_TOK * DIM_ / 4;        // activation float4 count
    const int nw4 = DIM_ * DIM_ / 4;           // weight float4 count
    const int SB = 256;
    dim3 gact((nact4 + SB - 1) / SB), gw((nw4 + SB - 1) / SB);
    dim3 gg(DIM_ / 128, (L_TOK + 127) / 128);

    // split activations x
    split_kernel<<<gact, SB>>>((const float4*)x, (__nv_bfloat162*)ah,
                               (__nv_bfloat162*)al, nact4);
    // Q/K/V projections
    split_kernel<<<gw, SB>>>((const float4*)wq, (__nv_bfloat162*)wh,
                             (__nv_bfloat162*)wl, nw4);
    gemm_bf16s_kernel<<<gg, 256>>>(ah, al, wh, wl, bq, q, L_TOK);
    split_kernel<<<gw, SB>>>((const float4*)wk, (__nv_bfloat162*)wh,
                             (__nv_bfloat162*)wl, nw4);
    gemm_bf16s_kernel<<<gg, 256>>>(ah, al, wh, wl, bk, k, L_TOK);
    split_kernel<<<gw, SB>>>((const float4*)wv, (__nv_bfloat162*)wh,
                             (__nv_bfloat162*)wl, nw4);
    gemm_bf16s_kernel<<<gg, 256>>>(ah, al, wh, wl, bv, v, L_TOK);

    norm_rope_kernel<<<L_TOK, 256>>>(q, gq, fr);
    norm_rope_kernel<<<L_TOK, 256>>>(k, gk, fr);

    size_t smem = (size_t)(128 * 68 + 128 * 68 + 64 * 68 + 192) * sizeof(float);
    cudaFuncSetAttribute(attn_kernel, cudaFuncAttributeMaxDynamicSharedMemorySize,
                         (int)smem);
    attn_kernel<<<dim3((L_TOK + 63) / 64, NH), 256, smem>>>(q, k, v, a);

    // output projection
    split_kernel<<<gact, SB>>>((const float4*)a, (__nv_bfloat162*)ah,
                               (__nv_bfloat162*)al, nact4);
    split_kernel<<<gw, SB>>>((const float4*)wo, (__nv_bfloat162*)wh,
                             (__nv_bfloat162*)wl, nw4);
    gemm_bf16s_kernel<<<gg, 256>>>(ah, al, wh, wl, bo, out, L_TOK);
}

// round 4
// speedup vs baseline: 2.6200x; 2.2214x over previous
#include <cuda_runtime.h>
#include <cuda_bf16.h>
#include <math.h>

#define L_TOK  4680
#define DIM_   1536
#define NH     12
#define HD     128
#define FRAME  1560
#define WW     52
#define SINK   1
#define LOCAL  2

// Scratch (no cudaMalloc allowed)
__device__ float g_q[L_TOK * DIM_];
__device__ float g_k[L_TOK * DIM_];
__device__ float g_v[L_TOK * DIM_];
__device__ float g_a[L_TOK * DIM_];
__device__ __nv_bfloat16 g_act_hi[L_TOK * DIM_];
__device__ __nv_bfloat16 g_act_lo[L_TOK * DIM_];
__device__ __nv_bfloat16 g_w_hi[DIM_ * DIM_];
__device__ __nv_bfloat16 g_w_lo[DIM_ * DIM_];
__device__ __nv_bfloat16 g_qh[L_TOK * DIM_];
__device__ __nv_bfloat16 g_ql[L_TOK * DIM_];
__device__ __nv_bfloat16 g_kh[L_TOK * DIM_];
__device__ __nv_bfloat16 g_kl[L_TOK * DIM_];
__device__ __nv_bfloat16 g_vh[L_TOK * DIM_];
__device__ __nv_bfloat16 g_vl[L_TOK * DIM_];

// ---------------------------------------------------------------------------
// Split fp32 -> (hi, lo) bf16 planes.  x ~= hi + lo, |x - hi - lo| ~ 2^-18 |x|
// ---------------------------------------------------------------------------
__global__ void split_kernel(const float4* __restrict__ src,
                             __nv_bfloat162* __restrict__ hi,
                             __nv_bfloat162* __restrict__ lo,
                             int n4) {
    int i = blockIdx.x * blockDim.x + threadIdx.x;
    if (i >= n4) return;
    float4 f = src[i];
    __nv_bfloat16 h0 = __float2bfloat16_rn(f.x);
    __nv_bfloat16 h1 = __float2bfloat16_rn(f.y);
    __nv_bfloat16 h2 = __float2bfloat16_rn(f.z);
    __nv_bfloat16 h3 = __float2bfloat16_rn(f.w);
    __nv_bfloat16 l0 = __float2bfloat16_rn(f.x - __bfloat162float(h0));
    __nv_bfloat16 l1 = __float2bfloat16_rn(f.y - __bfloat162float(h1));
    __nv_bfloat16 l2 = __float2bfloat16_rn(f.z - __bfloat162float(h2));
    __nv_bfloat16 l3 = __float2bfloat16_rn(f.w - __bfloat162float(h3));
    hi[i * 2 + 0] = __halves2bfloat162(h0, h1);
    hi[i * 2 + 1] = __halves2bfloat162(h2, h3);
    lo[i * 2 + 0] = __halves2bfloat162(l0, l1);
    lo[i * 2 + 1] = __halves2bfloat162(l2, l3);
}

// ---------------------------------------------------------------------------
__device__ __forceinline__ void mma_bf16(float* c, const unsigned* a,
                                         unsigned b0, unsigned b1) {
    asm volatile(
        "mma.sync.aligned.m16n8k16.row.col.f32.bf16.bf16.f32 "
        "{%0,%1,%2,%3}, {%4,%5,%6,%7}, {%8,%9}, {%0,%1,%2,%3};"
        : "+f"(c[0]), "+f"(c[1]), "+f"(c[2]), "+f"(c[3])
        : "r"(a[0]), "r"(a[1]), "r"(a[2]), "r"(a[3]), "r"(b0), "r"(b1));
}

__device__ __forceinline__ void split2(float a, float b, unsigned& h, unsigned& l) {
    __nv_bfloat162 hv = __floats2bfloat162_rn(a, b);
    float2 hf = __bfloat1622float2(hv);
    __nv_bfloat162 lv = __floats2bfloat162_rn(a - hf.x, b - hf.y);
    h = *reinterpret_cast<unsigned*>(&hv);
    l = *reinterpret_cast<unsigned*>(&lv);
}

// ---------------------------------------------------------------------------
// C[M,N] = A[M,K] @ B[N,K]^T + bias, split-bf16 compensated tensor-core GEMM.
// (verified in round 3; unchanged)
// ---------------------------------------------------------------------------
#define GK 1536
#define SPITCH 40

__global__ __launch_bounds__(256, 2)
void gemm_bf16s_kernel(const __nv_bfloat16* __restrict__ Ah,
                       const __nv_bfloat16* __restrict__ Al,
                       const __nv_bfloat16* __restrict__ Bh,
                       const __nv_bfloat16* __restrict__ Bl,
                       const float* __restrict__ bias,
                       float* __restrict__ C, int M) {
    __shared__ __nv_bfloat16 Ash[128 * SPITCH];
    __shared__ __nv_bfloat16 Asl[128 * SPITCH];
    __shared__ __nv_bfloat16 Bsh[128 * SPITCH];
    __shared__ __nv_bfloat16 Bsl[128 * SPITCH];

    const int tid = threadIdx.x;
    const int lane = tid & 31, wid = tid >> 5;
    const int wm = (wid & 1) * 64;
    const int wn = (wid >> 1) * 32;
    const int m0 = blockIdx.y * 128, n0 = blockIdx.x * 128;

    float acc[4][4][4];
#pragma unroll
    for (int i = 0; i < 4; i++)
#pragma unroll
        for (int j = 0; j < 4; j++)
#pragma unroll
            for (int r = 0; r < 4; r++) acc[i][j][r] = 0.f;

    const int ldrow = tid >> 1;
    const int ldhalf = (tid & 1) * 16;
    const bool mok = (m0 + ldrow) < M;
    const size_t a_off = (size_t)(m0 + ldrow) * GK + ldhalf;
    const size_t b_off = (size_t)(n0 + ldrow) * GK + ldhalf;

    const int quad = lane >> 2, tq = (lane & 3) * 2;

    for (int k0 = 0; k0 < GK; k0 += 32) {
        uint4 z = make_uint4(0u, 0u, 0u, 0u);
        uint4 vah0 = z, vah1 = z, val0 = z, val1 = z;
        if (mok) {
            const uint4* p = (const uint4*)(Ah + a_off + k0);
            vah0 = p[0]; vah1 = p[1];
            p = (const uint4*)(Al + a_off + k0);
            val0 = p[0]; val1 = p[1];
        }
        const uint4* pb = (const uint4*)(Bh + b_off + k0);
        uint4 vbh0 = pb[0], vbh1 = pb[1];
        pb = (const uint4*)(Bl + b_off + k0);
        uint4 vbl0 = pb[0], vbl1 = pb[1];

        uint4* s = (uint4*)(Ash + ldrow * SPITCH + ldhalf);
        s[0] = vah0; s[1] = vah1;
        s = (uint4*)(Asl + ldrow * SPITCH + ldhalf);
        s[0] = val0; s[1] = val1;
        s = (uint4*)(Bsh + ldrow * SPITCH + ldhalf);
        s[0] = vbh0; s[1] = vbh1;
        s = (uint4*)(Bsl + ldrow * SPITCH + ldhalf);
        s[0] = vbl0; s[1] = vbl1;
        __syncthreads();

#pragma unroll
        for (int ks = 0; ks < 2; ks++) {
            const int kb = ks * 16;
            unsigned ah[4][4], al[4][4];
#pragma unroll
            for (int mt = 0; mt < 4; mt++) {
                int r = wm + mt * 16 + quad;
                ah[mt][0] = *(const unsigned*)(Ash + r * SPITCH + kb + tq);
                ah[mt][1] = *(const unsigned*)(Ash + (r + 8) * SPITCH + kb + tq);
                ah[mt][2] = *(const unsigned*)(Ash + r * SPITCH + kb + tq + 8);
                ah[mt][3] = *(const unsigned*)(Ash + (r + 8) * SPITCH + kb + tq + 8);
                al[mt][0] = *(const unsigned*)(Asl + r * SPITCH + kb + tq);
                al[mt][1] = *(const unsigned*)(Asl + (r + 8) * SPITCH + kb + tq);
                al[mt][2] = *(const unsigned*)(Asl + r * SPITCH + kb + tq + 8);
                al[mt][3] = *(const unsigned*)(Asl + (r + 8) * SPITCH + kb + tq + 8);
            }
#pragma unroll
            for (int nt = 0; nt < 4; nt++) {
                int bn = wn + nt * 8 + quad;
                unsigned bh0 = *(const unsigned*)(Bsh + bn * SPITCH + kb + tq);
                unsigned bh1 = *(const unsigned*)(Bsh + bn * SPITCH + kb + tq + 8);
                unsigned bl0 = *(const unsigned*)(Bsl + bn * SPITCH + kb + tq);
                unsigned bl1 = *(const unsigned*)(Bsl + bn * SPITCH + kb + tq + 8);
#pragma unroll
                for (int mt = 0; mt < 4; mt++) {
                    mma_bf16(acc[mt][nt], ah[mt], bh0, bh1);
                    mma_bf16(acc[mt][nt], al[mt], bh0, bh1);
                    mma_bf16(acc[mt][nt], ah[mt], bl0, bl1);
                }
            }
        }
        __syncthreads();
    }

#pragma unroll
    for (int mt = 0; mt < 4; mt++) {
        int r0 = m0 + wm + mt * 16 + quad;
#pragma unroll
        for (int nt = 0; nt < 4; nt++) {
            int col = n0 + wn + nt * 8 + tq;
            float b0 = bias[col], b1 = bias[col + 1];
            if (r0 < M) {
                float2 v = make_float2(acc[mt][nt][0] + b0, acc[mt][nt][1] + b1);
                *(float2*)(C + (size_t)r0 * GK + col) = v;
            }
            if (r0 + 8 < M) {
                float2 v = make_float2(acc[mt][nt][2] + b0, acc[mt][nt][3] + b1);
                *(float2*)(C + (size_t)(r0 + 8) * GK + col) = v;
            }
        }
    }
}

// ---------------------------------------------------------------------------
// In-place RMSNorm + 3D RoPE.  One block per token.  (verified; unchanged)
// ---------------------------------------------------------------------------
__global__ void norm_rope_kernel(float* __restrict__ data,
                                 const float* __restrict__ g,
                                 const float* __restrict__ freqs) {
    const int t = blockIdx.x;
    const int tid = threadIdx.x;
    float* row = data + (size_t)t * DIM_;

    float ss = 0.f;
    for (int c = tid; c < DIM_; c += 256) { float v = row[c]; ss += v * v; }
#pragma unroll
    for (int o = 16; o; o >>= 1) ss += __shfl_xor_sync(0xffffffffu, ss, o);

    __shared__ float red[8];
    __shared__ float inv_s;
    if ((tid & 31) == 0) red[tid >> 5] = ss;
    __syncthreads();
    if (tid == 0) {
        float tot = 0.f;
#pragma unroll
        for (int i = 0; i < 8; i++) tot += red[i];
        inv_s = rsqrtf(tot / (float)DIM_ + 1e-6f);
    }
    __syncthreads();
    const float inv = inv_s;

    const int f = t / FRAME, rem = t % FRAME;
    const int hh = rem / WW, ww = rem % WW;

    for (int p = tid; p < DIM_ / 2; p += 256) {
        int pin = p & 63;
        int pos = (pin < 22) ? f : ((pin < 43) ? hh : ww);
        float cs = freqs[(pos * 64 + pin) * 2 + 0];
        float sn = freqs[(pos * 64 + pin) * 2 + 1];
        int c = p * 2;
        float a = row[c]     * inv * g[c];
        float b = row[c + 1] * inv * g[c + 1];
        row[c]     = a * cs - b * sn;
        row[c + 1] = a * sn + b * cs;
    }
}

// ---------------------------------------------------------------------------
// Tensor-core flash attention, split-bf16 3-pass for QK^T and PV.
// BM=128 (8 warps x 16 rows), BN=64 keys/iter, m16n8k16.
// smem: Q hi/lo [128][136], K hi/lo [64][136], V hi/lo (d-major) [128][72].
// ---------------------------------------------------------------------------
#define QP 136   // Q/K smem pitch in bf16
#define VP 72    // V smem pitch in bf16

__global__ __launch_bounds__(256, 1)
void attn_mma_kernel(const __nv_bfloat16* __restrict__ Qh,
                     const __nv_bfloat16* __restrict__ Ql,
                     const __nv_bfloat16* __restrict__ Kh,
                     const __nv_bfloat16* __restrict__ Kl,
                     const __nv_bfloat16* __restrict__ Vh,
                     const __nv_bfloat16* __restrict__ Vl,
                     float* __restrict__ O) {
    extern __shared__ __nv_bfloat16 smb[];
    __nv_bfloat16* sQh = smb;
    __nv_bfloat16* sQl = sQh + 128 * QP;
    __nv_bfloat16* sKh = sQl + 128 * QP;
    __nv_bfloat16* sKl = sKh + 64 * QP;
    __nv_bfloat16* sVh = sKl + 64 * QP;
    __nv_bfloat16* sVl = sVh + 128 * VP;

    const int tid = threadIdx.x;
    const int lane = tid & 31, wid = tid >> 5;
    const int g = lane >> 2, tq2 = (lane & 3) * 2;
    const int h = blockIdx.y;
    const int q0 = blockIdx.x * 128;
    const int r0 = wid * 16;
    const float scale = 0.08838834764831845f;

    // ---- load Q tile (both planes), row-major ----
#pragma unroll
    for (int it = 0; it < 8; it++) {
        int idx = it * 256 + tid;
        int row = idx >> 4, ch = (idx & 15) * 8;
        uint4 zh = make_uint4(0, 0, 0, 0), zl = zh;
        if (q0 + row < L_TOK) {
            size_t off = (size_t)(q0 + row) * DIM_ + h * HD + ch;
            zh = *(const uint4*)(Qh + off);
            zl = *(const uint4*)(Ql + off);
        }
        *(uint4*)(sQh + row * QP + ch) = zh;
        *(uint4*)(sQl + row * QP + ch) = zl;
    }

    float m_pr0 = -INFINITY, m_pr1 = -INFINITY;
    float l0 = 0.f, l1 = 0.f;
    float oacc[16][4];
#pragma unroll
    for (int i = 0; i < 16; i++)
#pragma unroll
        for (int j = 0; j < 4; j++) oacc[i][j] = 0.f;

    const int row_g0 = q0 + r0 + g, row_g1 = row_g0 + 8;
    const int qf0 = min(row_g0, L_TOK - 1) / FRAME;
    const int qf1 = min(row_g1, L_TOK - 1) / FRAME;

    const int qmax = min(q0 + 127, L_TOK - 1);
    const int kend = min(L_TOK, (qmax / FRAME + 1) * FRAME);
    const int ntiles = (kend + 63) >> 6;

    for (int t = 0; t < ntiles; t++) {
        const int k0 = t * 64;
        __syncthreads();
        // K tile row-major
#pragma unroll
        for (int it = 0; it < 4; it++) {
            int idx = it * 256 + tid;
            int row = idx >> 4, ch = (idx & 15) * 8;
            uint4 zh = make_uint4(0, 0, 0, 0), zl = zh;
            if (k0 + row < L_TOK) {
                size_t off = (size_t)(k0 + row) * DIM_ + h * HD + ch;
                zh = *(const uint4*)(Kh + off);
                zl = *(const uint4*)(Kl + off);
            }
            *(uint4*)(sKh + row * QP + ch) = zh;
            *(uint4*)(sKl + row * QP + ch) = zl;
        }
        // V tile transposed to d-major
#pragma unroll
        for (int it = 0; it < 4; it++) {
            int idx = it * 256 + tid;
            int key = idx & 63, dc = (idx >> 6) * 8;
            uint4 zh = make_uint4(0, 0, 0, 0), zl = zh;
            if (k0 + key < L_TOK) {
                size_t off = (size_t)(k0 + key) * DIM_ + h * HD + dc;
                zh = *(const uint4*)(Vh + off);
                zl = *(const uint4*)(Vl + off);
            }
            const __nv_bfloat16* eh = reinterpret_cast<const __nv_bfloat16*>(&zh);
            const __nv_bfloat16* el = reinterpret_cast<const __nv_bfloat16*>(&zl);
#pragma unroll
            for (int e = 0; e < 8; e++) {
                sVh[(dc + e) * VP + key] = eh[e];
                sVl[(dc + e) * VP + key] = el[e];
            }
        }
        __syncthreads();

        // ---- S = Q K^T (3-pass split) ----
        float sacc[8][4];
#pragma unroll
        for (int i = 0; i < 8; i++)
#pragma unroll
            for (int j = 0; j < 4; j++) sacc[i][j] = 0.f;

#pragma unroll
        for (int kc = 0; kc < 8; kc++) {
            const int kb = kc * 16 + tq2;
            unsigned qh[4], ql[4];
            qh[0] = *(const unsigned*)(sQh + (r0 + g) * QP + kb);
            qh[1] = *(const unsigned*)(sQh + (r0 + g + 8) * QP + kb);
            qh[2] = *(const unsigned*)(sQh + (r0 + g) * QP + kb + 8);
            qh[3] = *(const unsigned*)(sQh + (r0 + g + 8) * QP + kb + 8);
            ql[0] = *(const unsigned*)(sQl + (r0 + g) * QP + kb);
            ql[1] = *(const unsigned*)(sQl + (r0 + g + 8) * QP + kb);
            ql[2] = *(const unsigned*)(sQl + (r0 + g) * QP + kb + 8);
            ql[3] = *(const unsigned*)(sQl + (r0 + g + 8) * QP + kb + 8);
#pragma unroll
            for (int nt = 0; nt < 8; nt++) {
                const int kr = nt * 8 + g;
                unsigned kh0 = *(const unsigned*)(sKh + kr * QP + kb);
                unsigned kh1 = *(const unsigned*)(sKh + kr * QP + kb + 8);
                unsigned kl0 = *(const unsigned*)(sKl + kr * QP + kb);
                unsigned kl1 = *(const unsigned*)(sKl + kr * QP + kb + 8);
                mma_bf16(sacc[nt], qh, kh0, kh1);
                mma_bf16(sacc[nt], ql, kh0, kh1);
                mma_bf16(sacc[nt], qh, kl0, kl1);
            }
        }

        // ---- mask + scale + online softmax ----
        float mloc0 = -INFINITY, mloc1 = -INFINITY;
#pragma unroll
        for (int nt = 0; nt < 8; nt++) {
            int c0 = k0 + nt * 8 + tq2, c1 = c0 + 1;
            int kf0 = c0 / FRAME, kf1 = c1 / FRAME;
            bool a00 = (c0 < L_TOK) && kf0 <= qf0 && (kf0 < SINK || qf0 - kf0 < LOCAL);
            bool a10 = (c1 < L_TOK) && kf1 <= qf0 && (kf1 < SINK || qf0 - kf1 < LOCAL);
            bool a01 = (c0 < L_TOK) && kf0 <= qf1 && (kf0 < SINK || qf1 - kf0 < LOCAL);
            bool a11 = (c1 < L_TOK) && kf1 <= qf1 && (kf1 < SINK || qf1 - kf1 < LOCAL);
            sacc[nt][0] = a00 ? sacc[nt][0] * scale : -INFINITY;
            sacc[nt][1] = a10 ? sacc[nt][1] * scale : -INFINITY;
            sacc[nt][2] = a01 ? sacc[nt][2] * scale : -INFINITY;
            sacc[nt][3] = a11 ? sacc[nt][3] * scale : -INFINITY;
            mloc0 = fmaxf(mloc0, fmaxf(sacc[nt][0], sacc[nt][1]));
            mloc1 = fmaxf(mloc1, fmaxf(sacc[nt][2], sacc[nt][3]));
        }
        mloc0 = fmaxf(mloc0, __shfl_xor_sync(0xffffffffu, mloc0, 1));
        mloc0 = fmaxf(mloc0, __shfl_xor_sync(0xffffffffu, mloc0, 2));
        mloc1 = fmaxf(mloc1, __shfl_xor_sync(0xffffffffu, mloc1, 1));
        mloc1 = fmaxf(mloc1, __shfl_xor_sync(0xffffffffu, mloc1, 2));

        float mn0 = fmaxf(m_pr0, mloc0), mn1 = fmaxf(m_pr1, mloc1);
        float alpha0 = __expf(m_pr0 - mn0), alpha1 = __expf(m_pr1 - mn1);
        m_pr0 = mn0; m_pr1 = mn1;

        float rs0 = 0.f, rs1 = 0.f;
#pragma unroll
        for (int nt = 0; nt < 8; nt++) {
            sacc[nt][0] = __expf(sacc[nt][0] - mn0);
            sacc[nt][1] = __expf(sacc[nt][1] - mn0);
            sacc[nt][2] = __expf(sacc[nt][2] - mn1);
            sacc[nt][3] = __expf(sacc[nt][3] - mn1);
            rs0 += sacc[nt][0] + sacc[nt][1];
            rs1 += sacc[nt][2] + sacc[nt][3];
        }
        rs0 += __shfl_xor_sync(0xffffffffu, rs0, 1);
        rs0 += __shfl_xor_sync(0xffffffffu, rs0, 2);
        rs1 += __shfl_xor_sync(0xffffffffu, rs1, 1);
        rs1 += __shfl_xor_sync(0xffffffffu, rs1, 2);
        l0 = l0 * alpha0 + rs0;
        l1 = l1 * alpha1 + rs1;

#pragma unroll
        for (int dt = 0; dt < 16; dt++) {
            oacc[dt][0] *= alpha0; oacc[dt][1] *= alpha0;
            oacc[dt][2] *= alpha1; oacc[dt][3] *= alpha1;
        }

        // ---- O += P V (3-pass split, P split in registers) ----
#pragma unroll
        for (int kc2 = 0; kc2 < 4; kc2++) {
            unsigned pah[4], pal[4];
            split2(sacc[2 * kc2][0],     sacc[2 * kc2][1],     pah[0], pal[0]);
            split2(sacc[2 * kc2][2],     sacc[2 * kc2][3],     pah[1], pal[1]);
            split2(sacc[2 * kc2 + 1][0], sacc[2 * kc2 + 1][1], pah[2], pal[2]);
            split2(sacc[2 * kc2 + 1][2], sacc[2 * kc2 + 1][3], pah[3], pal[3]);
            const int kb2 = kc2 * 16 + tq2;
#pragma unroll
            for (int dt = 0; dt < 16; dt++) {
                const int vr = dt * 8 + g;
                unsigned vh0 = *(const unsigned*)(sVh + vr * VP + kb2);
                unsigned vh1 = *(const unsigned*)(sVh + vr * VP + kb2 + 8);
                unsigned vl0 = *(const unsigned*)(sVl + vr * VP + kb2);
                unsigned vl1 = *(const unsigned*)(sVl + vr * VP + kb2 + 8);
                mma_bf16(oacc[dt], pah, vh0, vh1);
                mma_bf16(oacc[dt], pal, vh0, vh1);
                mma_bf16(oacc[dt], pah, vl0, vl1);
            }
        }
    }

    // ---- epilogue ----
    const float li0 = 1.f / l0, li1 = 1.f / l1;
#pragma unroll
    for (int dt = 0; dt < 16; dt++) {
        const int d = dt * 8 + tq2;
        if (row_g0 < L_TOK) {
            float2 v = make_float2(oacc[dt][0] * li0, oacc[dt][1] * li0);
            *(float2*)(O + (size_t)row_g0 * DIM_ + h * HD + d) = v;
        }
        if (row_g1 < L_TOK) {
            float2 v = make_float2(oacc[dt][2] * li1, oacc[dt][3] * li1);
            *(float2*)(O + (size_t)row_g1 * DIM_ + h * HD + d) = v;
        }
    }
}

// ---------------------------------------------------------------------------
extern "C" void kernel_launch(void* const* d_in, const int* in_sizes, int n_in,
                              void* d_out, int out_size) {
    const float* x  = (const float*)d_in[0];
    const float* wq = (const float*)d_in[1];
    const float* bq = (const float*)d_in[2];
    const float* wk = (const float*)d_in[3];
    const float* bk = (const float*)d_in[4];
    const float* wv = (const float*)d_in[5];
    const float* bv = (const float*)d_in[6];
    const float* wo = (const float*)d_in[7];
    const float* bo = (const float*)d_in[8];
    const float* gq = (const float*)d_in[9];
    const float* gk = (const float*)d_in[10];
    const float* fr = (const float*)d_in[11];
    float* out = (float*)d_out;

    float *q, *k, *v, *a;
    __nv_bfloat16 *ah, *al, *wh, *wl, *qh, *ql, *kh, *kl, *vh, *vl;
    cudaGetSymbolAddress((void**)&q, g_q);
    cudaGetSymbolAddress((void**)&k, g_k);
    cudaGetSymbolAddress((void**)&v, g_v);
    cudaGetSymbolAddress((void**)&a, g_a);
    cudaGetSymbolAddress((void**)&ah, g_act_hi);
    cudaGetSymbolAddress((void**)&al, g_act_lo);
    cudaGetSymbolAddress((void**)&wh, g_w_hi);
    cudaGetSymbolAddress((void**)&wl, g_w_lo);
    cudaGetSymbolAddress((void**)&qh, g_qh);
    cudaGetSymbolAddress((void**)&ql, g_ql);
    cudaGetSymbolAddress((void**)&kh, g_kh);
    cudaGetSymbolAddress((void**)&kl, g_kl);
    cudaGetSymbolAddress((void**)&vh, g_vh);
    cudaGetSymbolAddress((void**)&vl, g_vl);

    const int nact4 = L_TOK * DIM_ / 4;
    const int nw4 = DIM_ * DIM_ / 4;
    const int SB = 256;
    dim3 gact((nact4 + SB - 1) / SB), gw((nw4 + SB - 1) / SB);
    dim3 gg(DIM_ / 128, (L_TOK + 127) / 128);

    split_kernel<<<gact, SB>>>((const float4*)x, (__nv_bfloat162*)ah,
                               (__nv_bfloat162*)al, nact4);
    split_kernel<<<gw, SB>>>((const float4*)wq, (__nv_bfloat162*)wh,
                             (__nv_bfloat162*)wl, nw4);
    gemm_bf16s_kernel<<<gg, 256>>>(ah, al, wh, wl, bq, q, L_TOK);
    split_kernel<<<gw, SB>>>((const float4*)wk, (__nv_bfloat162*)wh,
                             (__nv_bfloat162*)wl, nw4);
    gemm_bf16s_kernel<<<gg, 256>>>(ah, al, wh, wl, bk, k, L_TOK);
    split_kernel<<<gw, SB>>>((const float4*)wv, (__nv_bfloat162*)wh,
                             (__nv_bfloat162*)wl, nw4);
    gemm_bf16s_kernel<<<gg, 256>>>(ah, al, wh, wl, bv, v, L_TOK);

    norm_rope_kernel<<<L_TOK, 256>>>(q, gq, fr);
    norm_rope_kernel<<<L_TOK, 256>>>(k, gk, fr);

    // split q/k/v into bf16 hi/lo planes for tensor-core attention
    split_kernel<<<gact, SB>>>((const float4*)q, (__nv_bfloat162*)qh,
                               (__nv_bfloat162*)ql, nact4);
    split_kernel<<<gact, SB>>>((const float4*)k, (__nv_bfloat162*)kh,
                               (__nv_bfloat162*)kl, nact4);
    split_kernel<<<gact, SB>>>((const float4*)v, (__nv_bfloat162*)vh,
                               (__nv_bfloat162*)vl, nact4);

    size_t asmem = (size_t)(2 * 128 * QP + 2 * 64 * QP + 2 * 128 * VP) *
                   sizeof(__nv_bfloat16);
    cudaFuncSetAttribute(attn_mma_kernel,
                         cudaFuncAttributeMaxDynamicSharedMemorySize, (int)asmem);
    attn_mma_kernel<<<dim3((L_TOK + 127) / 128, NH), 256, asmem>>>(
        qh, ql, kh, kl, vh, vl, a);

    split_kernel<<<gact, SB>>>((const float4*)a, (__nv_bfloat162*)ah,
                               (__nv_bfloat162*)al, nact4);
    split_kernel<<<gw, SB>>>((const float4*)wo, (__nv_bfloat162*)wh,
                             (__nv_bfloat162*)wl, nw4);
    gemm_bf16s_kernel<<<gg, 256>>>(ah, al, wh, wl, bo, out, L_TOK);
}

// round 5
// speedup vs baseline: 2.9146x; 1.1124x over previous
#include <cuda_runtime.h>
#include <cuda_bf16.h>
#include <math.h>

#define L_TOK  4680
#define DIM_   1536
#define NH     12
#define HD     128
#define FRAME  1560
#define WW     52
#define SINK   1
#define LOCAL  2

// Scratch (no cudaMalloc allowed)
__device__ float g_q[L_TOK * DIM_];
__device__ float g_k[L_TOK * DIM_];
__device__ float g_v[L_TOK * DIM_];
__device__ float g_a[L_TOK * DIM_];
__device__ __nv_bfloat16 g_act_hi[L_TOK * DIM_];
__device__ __nv_bfloat16 g_act_lo[L_TOK * DIM_];
__device__ __nv_bfloat16 g_w_hi[DIM_ * DIM_];
__device__ __nv_bfloat16 g_w_lo[DIM_ * DIM_];
__device__ __nv_bfloat16 g_qh[L_TOK * DIM_];
__device__ __nv_bfloat16 g_ql[L_TOK * DIM_];
__device__ __nv_bfloat16 g_kh[L_TOK * DIM_];
__device__ __nv_bfloat16 g_kl[L_TOK * DIM_];
__device__ __nv_bfloat16 g_vh[L_TOK * DIM_];
__device__ __nv_bfloat16 g_vl[L_TOK * DIM_];

// ---------------------------------------------------------------------------
// Split fp32 -> (hi, lo) bf16 planes.
// ---------------------------------------------------------------------------
__global__ void split_kernel(const float4* __restrict__ src,
                             __nv_bfloat162* __restrict__ hi,
                             __nv_bfloat162* __restrict__ lo,
                             int n4) {
    int i = blockIdx.x * blockDim.x + threadIdx.x;
    if (i >= n4) return;
    float4 f = src[i];
    __nv_bfloat16 h0 = __float2bfloat16_rn(f.x);
    __nv_bfloat16 h1 = __float2bfloat16_rn(f.y);
    __nv_bfloat16 h2 = __float2bfloat16_rn(f.z);
    __nv_bfloat16 h3 = __float2bfloat16_rn(f.w);
    __nv_bfloat16 l0 = __float2bfloat16_rn(f.x - __bfloat162float(h0));
    __nv_bfloat16 l1 = __float2bfloat16_rn(f.y - __bfloat162float(h1));
    __nv_bfloat16 l2 = __float2bfloat16_rn(f.z - __bfloat162float(h2));
    __nv_bfloat16 l3 = __float2bfloat16_rn(f.w - __bfloat162float(h3));
    hi[i * 2 + 0] = __halves2bfloat162(h0, h1);
    hi[i * 2 + 1] = __halves2bfloat162(h2, h3);
    lo[i * 2 + 0] = __halves2bfloat162(l0, l1);
    lo[i * 2 + 1] = __halves2bfloat162(l2, l3);
}

// ---------------------------------------------------------------------------
__device__ __forceinline__ void mma_bf16(float* c, const unsigned* a,
                                         unsigned b0, unsigned b1) {
    asm volatile(
        "mma.sync.aligned.m16n8k16.row.col.f32.bf16.bf16.f32 "
        "{%0,%1,%2,%3}, {%4,%5,%6,%7}, {%8,%9}, {%0,%1,%2,%3};"
        : "+f"(c[0]), "+f"(c[1]), "+f"(c[2]), "+f"(c[3])
        : "r"(a[0]), "r"(a[1]), "r"(a[2]), "r"(a[3]), "r"(b0), "r"(b1));
}

__device__ __forceinline__ void split2(float a, float b, unsigned& h, unsigned& l) {
    __nv_bfloat162 hv = __floats2bfloat162_rn(a, b);
    float2 hf = __bfloat1622float2(hv);
    __nv_bfloat162 lv = __floats2bfloat162_rn(a - hf.x, b - hf.y);
    h = *reinterpret_cast<unsigned*>(&hv);
    l = *reinterpret_cast<unsigned*>(&lv);
}

__device__ __forceinline__ void cp16(void* s, const void* g, bool valid) {
    unsigned sa = (unsigned)__cvta_generic_to_shared(s);
    int sz = valid ? 16 : 0;
    asm volatile("cp.async.ca.shared.global [%0], [%1], 16, %2;"
                 :: "r"(sa), "l"(g), "r"(sz));
}

// ---------------------------------------------------------------------------
// GEMM v2: C[M,N] = A[M,K] @ B[N,K]^T + bias, split-bf16 3-pass.
// 128 threads (4 warps, 2x2), block 128x128, warp tile 64x64 (mt=4, nt=8),
// BK=32, cp.async double-buffered smem, no register spills.
// ---------------------------------------------------------------------------
#define GK 1536
#define SPITCH 40
#define GTILE (128 * SPITCH)

__global__ __launch_bounds__(128, 2)
void gemm_bf16s_v2(const __nv_bfloat16* __restrict__ Ah,
                   const __nv_bfloat16* __restrict__ Al,
                   const __nv_bfloat16* __restrict__ Bh,
                   const __nv_bfloat16* __restrict__ Bl,
                   const float* __restrict__ bias,
                   float* __restrict__ C, int M) {
    extern __shared__ __nv_bfloat16 smg[];
    // layout: [buf:2][plane:4 = Ah,Al,Bh,Bl][128*SPITCH]

    const int tid = threadIdx.x;
    const int lane = tid & 31, wid = tid >> 5;
    const int wm = (wid & 1) * 64, wn = (wid >> 1) * 64;
    const int m0 = blockIdx.y * 128, n0 = blockIdx.x * 128;
    const int quad = lane >> 2, tq = (lane & 3) * 2;

    float acc[4][8][4];
#pragma unroll
    for (int i = 0; i < 4; i++)
#pragma unroll
        for (int j = 0; j < 8; j++)
#pragma unroll
            for (int r = 0; r < 4; r++) acc[i][j][r] = 0.f;

    const int NK = GK / 32;  // 48

    // per-thread load map: 4 chunks of 16B per plane per k-iter
    // chunk idx = it*128+tid -> row = idx>>2, ch = (idx&3)*8 (bf16 units)
#define ISSUE_TILE(kt, buf)                                                   \
    {                                                                         \
        const int k0i = (kt) * 32;                                            \
        __nv_bfloat16* dAh = smg + ((buf) * 4 + 0) * GTILE;                   \
        __nv_bfloat16* dAl = smg + ((buf) * 4 + 1) * GTILE;                   \
        __nv_bfloat16* dBh = smg + ((buf) * 4 + 2) * GTILE;                   \
        __nv_bfloat16* dBl = smg + ((buf) * 4 + 3) * GTILE;                   \
        _Pragma("unroll")                                                     \
        for (int it = 0; it < 4; it++) {                                      \
            int idx = it * 128 + tid;                                         \
            int row = idx >> 2, ch = (idx & 3) * 8;                           \
            int arow = m0 + row;                                              \
            bool v = arow < M;                                                \
            int crow = v ? arow : (M - 1);                                    \
            size_t aoff = (size_t)crow * GK + k0i + ch;                       \
            size_t boff = (size_t)(n0 + row) * GK + k0i + ch;                 \
            cp16(dAh + row * SPITCH + ch, Ah + aoff, v);                      \
            cp16(dAl + row * SPITCH + ch, Al + aoff, v);                      \
            cp16(dBh + row * SPITCH + ch, Bh + boff, true);                   \
            cp16(dBl + row * SPITCH + ch, Bl + boff, true);                   \
        }                                                                     \
        asm volatile("cp.async.commit_group;");                               \
    }

    ISSUE_TILE(0, 0);

    for (int kt = 0; kt < NK; kt++) {
        const int buf = kt & 1;
        if (kt + 1 < NK) {
            ISSUE_TILE(kt + 1, buf ^ 1);
            asm volatile("cp.async.wait_group 1;");
        } else {
            asm volatile("cp.async.wait_group 0;");
        }
        __syncthreads();

        const __nv_bfloat16* cAh = smg + (buf * 4 + 0) * GTILE;
        const __nv_bfloat16* cAl = smg + (buf * 4 + 1) * GTILE;
        const __nv_bfloat16* cBh = smg + (buf * 4 + 2) * GTILE;
        const __nv_bfloat16* cBl = smg + (buf * 4 + 3) * GTILE;

#pragma unroll
        for (int ks = 0; ks < 2; ks++) {
            const int kb = ks * 16 + tq;
            unsigned ah[4][4], al[4][4];
#pragma unroll
            for (int mt = 0; mt < 4; mt++) {
                int r = wm + mt * 16 + quad;
                ah[mt][0] = *(const unsigned*)(cAh + r * SPITCH + kb);
                ah[mt][1] = *(const unsigned*)(cAh + (r + 8) * SPITCH + kb);
                ah[mt][2] = *(const unsigned*)(cAh + r * SPITCH + kb + 8);
                ah[mt][3] = *(const unsigned*)(cAh + (r + 8) * SPITCH + kb + 8);
                al[mt][0] = *(const unsigned*)(cAl + r * SPITCH + kb);
                al[mt][1] = *(const unsigned*)(cAl + (r + 8) * SPITCH + kb);
                al[mt][2] = *(const unsigned*)(cAl + r * SPITCH + kb + 8);
                al[mt][3] = *(const unsigned*)(cAl + (r + 8) * SPITCH + kb + 8);
            }
#pragma unroll
            for (int nt = 0; nt < 8; nt++) {
                int bn = wn + nt * 8 + quad;
                unsigned bh0 = *(const unsigned*)(cBh + bn * SPITCH + kb);
                unsigned bh1 = *(const unsigned*)(cBh + bn * SPITCH + kb + 8);
                unsigned bl0 = *(const unsigned*)(cBl + bn * SPITCH + kb);
                unsigned bl1 = *(const unsigned*)(cBl + bn * SPITCH + kb + 8);
#pragma unroll
                for (int mt = 0; mt < 4; mt++) {
                    mma_bf16(acc[mt][nt], ah[mt], bh0, bh1);
                    mma_bf16(acc[mt][nt], al[mt], bh0, bh1);
                    mma_bf16(acc[mt][nt], ah[mt], bl0, bl1);
                }
            }
        }
        __syncthreads();
    }

    // epilogue
#pragma unroll
    for (int mt = 0; mt < 4; mt++) {
        int r0 = m0 + wm + mt * 16 + quad;
#pragma unroll
        for (int nt = 0; nt < 8; nt++) {
            int col = n0 + wn + nt * 8 + tq;
            float b0 = bias[col], b1 = bias[col + 1];
            if (r0 < M) {
                float2 v = make_float2(acc[mt][nt][0] + b0, acc[mt][nt][1] + b1);
                *(float2*)(C + (size_t)r0 * GK + col) = v;
            }
            if (r0 + 8 < M) {
                float2 v = make_float2(acc[mt][nt][2] + b0, acc[mt][nt][3] + b1);
                *(float2*)(C + (size_t)(r0 + 8) * GK + col) = v;
            }
        }
    }
}

// ---------------------------------------------------------------------------
// In-place RMSNorm + 3D RoPE.  One block per token.  (verified; unchanged)
// ---------------------------------------------------------------------------
__global__ void norm_rope_kernel(float* __restrict__ data,
                                 const float* __restrict__ g,
                                 const float* __restrict__ freqs) {
    const int t = blockIdx.x;
    const int tid = threadIdx.x;
    float* row = data + (size_t)t * DIM_;

    float ss = 0.f;
    for (int c = tid; c < DIM_; c += 256) { float v = row[c]; ss += v * v; }
#pragma unroll
    for (int o = 16; o; o >>= 1) ss += __shfl_xor_sync(0xffffffffu, ss, o);

    __shared__ float red[8];
    __shared__ float inv_s;
    if ((tid & 31) == 0) red[tid >> 5] = ss;
    __syncthreads();
    if (tid == 0) {
        float tot = 0.f;
#pragma unroll
        for (int i = 0; i < 8; i++) tot += red[i];
        inv_s = rsqrtf(tot / (float)DIM_ + 1e-6f);
    }
    __syncthreads();
    const float inv = inv_s;

    const int f = t / FRAME, rem = t % FRAME;
    const int hh = rem / WW, ww = rem % WW;

    for (int p = tid; p < DIM_ / 2; p += 256) {
        int pin = p & 63;
        int pos = (pin < 22) ? f : ((pin < 43) ? hh : ww);
        float cs = freqs[(pos * 64 + pin) * 2 + 0];
        float sn = freqs[(pos * 64 + pin) * 2 + 1];
        int c = p * 2;
        float a = row[c]     * inv * g[c];
        float b = row[c + 1] * inv * g[c + 1];
        row[c]     = a * cs - b * sn;
        row[c + 1] = a * sn + b * cs;
    }
}

// ---------------------------------------------------------------------------
// Tensor-core flash attention, split-bf16 3-pass.  (verified R4; unchanged)
// ---------------------------------------------------------------------------
#define QP 136
#define VP 72

__global__ __launch_bounds__(256, 1)
void attn_mma_kernel(const __nv_bfloat16* __restrict__ Qh,
                     const __nv_bfloat16* __restrict__ Ql,
                     const __nv_bfloat16* __restrict__ Kh,
                     const __nv_bfloat16* __restrict__ Kl,
                     const __nv_bfloat16* __restrict__ Vh,
                     const __nv_bfloat16* __restrict__ Vl,
                     float* __restrict__ O) {
    extern __shared__ __nv_bfloat16 smb[];
    __nv_bfloat16* sQh = smb;
    __nv_bfloat16* sQl = sQh + 128 * QP;
    __nv_bfloat16* sKh = sQl + 128 * QP;
    __nv_bfloat16* sKl = sKh + 64 * QP;
    __nv_bfloat16* sVh = sKl + 64 * QP;
    __nv_bfloat16* sVl = sVh + 128 * VP;

    const int tid = threadIdx.x;
    const int lane = tid & 31, wid = tid >> 5;
    const int g = lane >> 2, tq2 = (lane & 3) * 2;
    const int h = blockIdx.y;
    const int q0 = blockIdx.x * 128;
    const int r0 = wid * 16;
    const float scale = 0.08838834764831845f;

#pragma unroll
    for (int it = 0; it < 8; it++) {
        int idx = it * 256 + tid;
        int row = idx >> 4, ch = (idx & 15) * 8;
        uint4 zh = make_uint4(0, 0, 0, 0), zl = zh;
        if (q0 + row < L_TOK) {
            size_t off = (size_t)(q0 + row) * DIM_ + h * HD + ch;
            zh = *(const uint4*)(Qh + off);
            zl = *(const uint4*)(Ql + off);
        }
        *(uint4*)(sQh + row * QP + ch) = zh;
        *(uint4*)(sQl + row * QP + ch) = zl;
    }

    float m_pr0 = -INFINITY, m_pr1 = -INFINITY;
    float l0 = 0.f, l1 = 0.f;
    float oacc[16][4];
#pragma unroll
    for (int i = 0; i < 16; i++)
#pragma unroll
        for (int j = 0; j < 4; j++) oacc[i][j] = 0.f;

    const int row_g0 = q0 + r0 + g, row_g1 = row_g0 + 8;
    const int qf0 = min(row_g0, L_TOK - 1) / FRAME;
    const int qf1 = min(row_g1, L_TOK - 1) / FRAME;

    const int qmax = min(q0 + 127, L_TOK - 1);
    const int kend = min(L_TOK, (qmax / FRAME + 1) * FRAME);
    const int ntiles = (kend + 63) >> 6;

    for (int t = 0; t < ntiles; t++) {
        const int k0 = t * 64;
        __syncthreads();
#pragma unroll
        for (int it = 0; it < 4; it++) {
            int idx = it * 256 + tid;
            int row = idx >> 4, ch = (idx & 15) * 8;
            uint4 zh = make_uint4(0, 0, 0, 0), zl = zh;
            if (k0 + row < L_TOK) {
                size_t off = (size_t)(k0 + row) * DIM_ + h * HD + ch;
                zh = *(const uint4*)(Kh + off);
                zl = *(const uint4*)(Kl + off);
            }
            *(uint4*)(sKh + row * QP + ch) = zh;
            *(uint4*)(sKl + row * QP + ch) = zl;
        }
#pragma unroll
        for (int it = 0; it < 4; it++) {
            int idx = it * 256 + tid;
            int key = idx & 63, dc = (idx >> 6) * 8;
            uint4 zh = make_uint4(0, 0, 0, 0), zl = zh;
            if (k0 + key < L_TOK) {
                size_t off = (size_t)(k0 + key) * DIM_ + h * HD + dc;
                zh = *(const uint4*)(Vh + off);
                zl = *(const uint4*)(Vl + off);
            }
            const __nv_bfloat16* eh = reinterpret_cast<const __nv_bfloat16*>(&zh);
            const __nv_bfloat16* el = reinterpret_cast<const __nv_bfloat16*>(&zl);
#pragma unroll
            for (int e = 0; e < 8; e++) {
                sVh[(dc + e) * VP + key] = eh[e];
                sVl[(dc + e) * VP + key] = el[e];
            }
        }
        __syncthreads();

        float sacc[8][4];
#pragma unroll
        for (int i = 0; i < 8; i++)
#pragma unroll
            for (int j = 0; j < 4; j++) sacc[i][j] = 0.f;

#pragma unroll
        for (int kc = 0; kc < 8; kc++) {
            const int kb = kc * 16 + tq2;
            unsigned qh[4], ql[4];
            qh[0] = *(const unsigned*)(sQh + (r0 + g) * QP + kb);
            qh[1] = *(const unsigned*)(sQh + (r0 + g + 8) * QP + kb);
            qh[2] = *(const unsigned*)(sQh + (r0 + g) * QP + kb + 8);
            qh[3] = *(const unsigned*)(sQh + (r0 + g + 8) * QP + kb + 8);
            ql[0] = *(const unsigned*)(sQl + (r0 + g) * QP + kb);
            ql[1] = *(const unsigned*)(sQl + (r0 + g + 8) * QP + kb);
            ql[2] = *(const unsigned*)(sQl + (r0 + g) * QP + kb + 8);
            ql[3] = *(const unsigned*)(sQl + (r0 + g + 8) * QP + kb + 8);
#pragma unroll
            for (int nt = 0; nt < 8; nt++) {
                const int kr = nt * 8 + g;
                unsigned kh0 = *(const unsigned*)(sKh + kr * QP + kb);
                unsigned kh1 = *(const unsigned*)(sKh + kr * QP + kb + 8);
                unsigned kl0 = *(const unsigned*)(sKl + kr * QP + kb);
                unsigned kl1 = *(const unsigned*)(sKl + kr * QP + kb + 8);
                mma_bf16(sacc[nt], qh, kh0, kh1);
                mma_bf16(sacc[nt], ql, kh0, kh1);
                mma_bf16(sacc[nt], qh, kl0, kl1);
            }
        }

        float mloc0 = -INFINITY, mloc1 = -INFINITY;
#pragma unroll
        for (int nt = 0; nt < 8; nt++) {
            int c0 = k0 + nt * 8 + tq2, c1 = c0 + 1;
            int kf0 = c0 / FRAME, kf1 = c1 / FRAME;
            bool a00 = (c0 < L_TOK) && kf0 <= qf0 && (kf0 < SINK || qf0 - kf0 < LOCAL);
            bool a10 = (c1 < L_TOK) && kf1 <= qf0 && (kf1 < SINK || qf0 - kf1 < LOCAL);
            bool a01 = (c0 < L_TOK) && kf0 <= qf1 && (kf0 < SINK || qf1 - kf0 < LOCAL);
            bool a11 = (c1 < L_TOK) && kf1 <= qf1 && (kf1 < SINK || qf1 - kf1 < LOCAL);
            sacc[nt][0] = a00 ? sacc[nt][0] * scale : -INFINITY;
            sacc[nt][1] = a10 ? sacc[nt][1] * scale : -INFINITY;
            sacc[nt][2] = a01 ? sacc[nt][2] * scale : -INFINITY;
            sacc[nt][3] = a11 ? sacc[nt][3] * scale : -INFINITY;
            mloc0 = fmaxf(mloc0, fmaxf(sacc[nt][0], sacc[nt][1]));
            mloc1 = fmaxf(mloc1, fmaxf(sacc[nt][2], sacc[nt][3]));
        }
        mloc0 = fmaxf(mloc0, __shfl_xor_sync(0xffffffffu, mloc0, 1));
        mloc0 = fmaxf(mloc0, __shfl_xor_sync(0xffffffffu, mloc0, 2));
        mloc1 = fmaxf(mloc1, __shfl_xor_sync(0xffffffffu, mloc1, 1));
        mloc1 = fmaxf(mloc1, __shfl_xor_sync(0xffffffffu, mloc1, 2));

        float mn0 = fmaxf(m_pr0, mloc0), mn1 = fmaxf(m_pr1, mloc1);
        float alpha0 = __expf(m_pr0 - mn0), alpha1 = __expf(m_pr1 - mn1);
        m_pr0 = mn0; m_pr1 = mn1;

        float rs0 = 0.f, rs1 = 0.f;
#pragma unroll
        for (int nt = 0; nt < 8; nt++) {
            sacc[nt][0] = __expf(sacc[nt][0] - mn0);
            sacc[nt][1] = __expf(sacc[nt][1] - mn0);
            sacc[nt][2] = __expf(sacc[nt][2] - mn1);
            sacc[nt][3] = __expf(sacc[nt][3] - mn1);
            rs0 += sacc[nt][0] + sacc[nt][1];
            rs1 += sacc[nt][2] + sacc[nt][3];
        }
        rs0 += __shfl_xor_sync(0xffffffffu, rs0, 1);
        rs0 += __shfl_xor_sync(0xffffffffu, rs0, 2);
        rs1 += __shfl_xor_sync(0xffffffffu, rs1, 1);
        rs1 += __shfl_xor_sync(0xffffffffu, rs1, 2);
        l0 = l0 * alpha0 + rs0;
        l1 = l1 * alpha1 + rs1;

#pragma unroll
        for (int dt = 0; dt < 16; dt++) {
            oacc[dt][0] *= alpha0; oacc[dt][1] *= alpha0;
            oacc[dt][2] *= alpha1; oacc[dt][3] *= alpha1;
        }

#pragma unroll
        for (int kc2 = 0; kc2 < 4; kc2++) {
            unsigned pah[4], pal[4];
            split2(sacc[2 * kc2][0],     sacc[2 * kc2][1],     pah[0], pal[0]);
            split2(sacc[2 * kc2][2],     sacc[2 * kc2][3],     pah[1], pal[1]);
            split2(sacc[2 * kc2 + 1][0], sacc[2 * kc2 + 1][1], pah[2], pal[2]);
            split2(sacc[2 * kc2 + 1][2], sacc[2 * kc2 + 1][3], pah[3], pal[3]);
            const int kb2 = kc2 * 16 + tq2;
#pragma unroll
            for (int dt = 0; dt < 16; dt++) {
                const int vr = dt * 8 + g;
                unsigned vh0 = *(const unsigned*)(sVh + vr * VP + kb2);
                unsigned vh1 = *(const unsigned*)(sVh + vr * VP + kb2 + 8);
                unsigned vl0 = *(const unsigned*)(sVl + vr * VP + kb2);
                unsigned vl1 = *(const unsigned*)(sVl + vr * VP + kb2 + 8);
                mma_bf16(oacc[dt], pah, vh0, vh1);
                mma_bf16(oacc[dt], pal, vh0, vh1);
                mma_bf16(oacc[dt], pah, vl0, vl1);
            }
        }
    }

    const float li0 = 1.f / l0, li1 = 1.f / l1;
#pragma unroll
    for (int dt = 0; dt < 16; dt++) {
        const int d = dt * 8 + tq2;
        if (row_g0 < L_TOK) {
            float2 v = make_float2(oacc[dt][0] * li0, oacc[dt][1] * li0);
            *(float2*)(O + (size_t)row_g0 * DIM_ + h * HD + d) = v;
        }
        if (row_g1 < L_TOK) {
            float2 v = make_float2(oacc[dt][2] * li1, oacc[dt][3] * li1);
            *(float2*)(O + (size_t)row_g1 * DIM_ + h * HD + d) = v;
        }
    }
}

// ---------------------------------------------------------------------------
extern "C" void kernel_launch(void* const* d_in, const int* in_sizes, int n_in,
                              void* d_out, int out_size) {
    const float* x  = (const float*)d_in[0];
    const float* wq = (const float*)d_in[1];
    const float* bq = (const float*)d_in[2];
    const float* wk = (const float*)d_in[3];
    const float* bk = (const float*)d_in[4];
    const float* wv = (const float*)d_in[5];
    const float* bv = (const float*)d_in[6];
    const float* wo = (const float*)d_in[7];
    const float* bo = (const float*)d_in[8];
    const float* gq = (const float*)d_in[9];
    const float* gk = (const float*)d_in[10];
    const float* fr = (const float*)d_in[11];
    float* out = (float*)d_out;

    float *q, *k, *v, *a;
    __nv_bfloat16 *ah, *al, *wh, *wl, *qh, *ql, *kh, *kl, *vh, *vl;
    cudaGetSymbolAddress((void**)&q, g_q);
    cudaGetSymbolAddress((void**)&k, g_k);
    cudaGetSymbolAddress((void**)&v, g_v);
    cudaGetSymbolAddress((void**)&a, g_a);
    cudaGetSymbolAddress((void**)&ah, g_act_hi);
    cudaGetSymbolAddress((void**)&al, g_act_lo);
    cudaGetSymbolAddress((void**)&wh, g_w_hi);
    cudaGetSymbolAddress((void**)&wl, g_w_lo);
    cudaGetSymbolAddress((void**)&qh, g_qh);
    cudaGetSymbolAddress((void**)&ql, g_ql);
    cudaGetSymbolAddress((void**)&kh, g_kh);
    cudaGetSymbolAddress((void**)&kl, g_kl);
    cudaGetSymbolAddress((void**)&vh, g_vh);
    cudaGetSymbolAddress((void**)&vl, g_vl);

    const int nact4 = L_TOK * DIM_ / 4;
    const int nw4 = DIM_ * DIM_ / 4;
    const int SB = 256;
    dim3 gact((nact4 + SB - 1) / SB), gw((nw4 + SB - 1) / SB);
    dim3 gg(DIM_ / 128, (L_TOK + 127) / 128);

    const int gsmem = 2 * 4 * GTILE * (int)sizeof(__nv_bfloat16);  // 81920
    cudaFuncSetAttribute(gemm_bf16s_v2,
                         cudaFuncAttributeMaxDynamicSharedMemorySize, gsmem);

    split_kernel<<<gact, SB>>>((const float4*)x, (__nv_bfloat162*)ah,
                               (__nv_bfloat162*)al, nact4);
    split_kernel<<<gw, SB>>>((const float4*)wq, (__nv_bfloat162*)wh,
                             (__nv_bfloat162*)wl, nw4);
    gemm_bf16s_v2<<<gg, 128, gsmem>>>(ah, al, wh, wl, bq, q, L_TOK);
    split_kernel<<<gw, SB>>>((const float4*)wk, (__nv_bfloat162*)wh,
                             (__nv_bfloat162*)wl, nw4);
    gemm_bf16s_v2<<<gg, 128, gsmem>>>(ah, al, wh, wl, bk, k, L_TOK);
    split_kernel<<<gw, SB>>>((const float4*)wv, (__nv_bfloat162*)wh,
                             (__nv_bfloat162*)wl, nw4);
    gemm_bf16s_v2<<<gg, 128, gsmem>>>(ah, al, wh, wl, bv, v, L_TOK);

    norm_rope_kernel<<<L_TOK, 256>>>(q, gq, fr);
    norm_rope_kernel<<<L_TOK, 256>>>(k, gk, fr);

    split_kernel<<<gact, SB>>>((const float4*)q, (__nv_bfloat162*)qh,
                               (__nv_bfloat162*)ql, nact4);
    split_kernel<<<gact, SB>>>((const float4*)k, (__nv_bfloat162*)kh,
                               (__nv_bfloat162*)kl, nact4);
    split_kernel<<<gact, SB>>>((const float4*)v, (__nv_bfloat162*)vh,
                               (__nv_bfloat162*)vl, nact4);

    size_t asmem = (size_t)(2 * 128 * QP + 2 * 64 * QP + 2 * 128 * VP) *
                   sizeof(__nv_bfloat16);
    cudaFuncSetAttribute(attn_mma_kernel,
                         cudaFuncAttributeMaxDynamicSharedMemorySize, (int)asmem);
    attn_mma_kernel<<<dim3((L_TOK + 127) / 128, NH), 256, asmem>>>(
        qh, ql, kh, kl, vh, vl, a);

    split_kernel<<<gact, SB>>>((const float4*)a, (__nv_bfloat162*)ah,
                               (__nv_bfloat162*)al, nact4);
    split_kernel<<<gw, SB>>>((const float4*)wo, (__nv_bfloat162*)wh,
                             (__nv_bfloat162*)wl, nw4);
    gemm_bf16s_v2<<<gg, 128, gsmem>>>(ah, al, wh, wl, bo, out, L_TOK);
}